// round 10
// baseline (speedup 1.0000x reference)
#include <cuda_runtime.h>
#include <math.h>

#define H 4096
#define HS 64
#define NH 64
#define TM 64
#define TD 128
#define GRID 444
#define NT 512

// ---------------- scratch (device globals) ----------------
__device__ float g_xn[H];
__device__ float g_sx[H];
__device__ float g_maa_part[128][5 * TM];
__device__ float g_m[5][H];
__device__ float g_wd1_part[64][TD];
__device__ float g_rkvg[4][H];
__device__ float g_gx[H];

__device__ unsigned long long g_bar = 0ULL;
__device__ unsigned int g_tickC;
__device__ unsigned int g_tickE;

__global__ void k_reset(void) {
    g_tickC = 0u;
    g_tickE = 0u;
}

__device__ __forceinline__ void grid_barrier() {
    __syncthreads();
    if (threadIdx.x == 0) {
        __threadfence();
        unsigned long long ticket = atomicAdd(&g_bar, 1ULL);
        unsigned long long goal = (ticket / GRID + 1ULL) * GRID;
        while (*((volatile unsigned long long*)&g_bar) < goal) { }
        __threadfence();
    }
    __syncthreads();
}

__device__ __forceinline__ void f4_fma(float4& a, float m, const float4& w) {
    a.x += m * w.x; a.y += m * w.y; a.z += m * w.z; a.w += m * w.w;
}
__device__ __forceinline__ void f4_add(float4& a, const float4& b) {
    a.x += b.x; a.y += b.y; a.z += b.z; a.w += b.w;
}

__global__ __launch_bounds__(NT, 3)
void k_mega(const float* __restrict__ x,
            const float* __restrict__ s1,
            const float* __restrict__ state2,
            const float* __restrict__ ln1_w,
            const float* __restrict__ ln1_b,
            const float* __restrict__ tmx,
            const float* __restrict__ tmw,
            const float* __restrict__ tmk,
            const float* __restrict__ tmv,
            const float* __restrict__ tmr,
            const float* __restrict__ tmg,
            const float* __restrict__ Wmaa1,
            const float* __restrict__ Wmaa2,
            const float* __restrict__ tdec,
            const float* __restrict__ Wd1,
            const float* __restrict__ Wd2,
            const float* __restrict__ faaaa,
            const float* __restrict__ Wr,
            const float* __restrict__ Wk,
            const float* __restrict__ Wv,
            const float* __restrict__ Wg,
            const float* __restrict__ Wo,
            const float* __restrict__ lnxw,
            const float* __restrict__ lnxb,
            float* __restrict__ d_out) {
    __shared__ __align__(16) float sm[5120];   // 20 KB
    __shared__ unsigned s_u;
    int t = threadIdx.x;
    int b = blockIdx.x;

    // ================= Phase A: LN stats (redundant) + token shift + maa1 partials ====
    {
        float lsum = 0.f, lsq = 0.f;
        const float4* x4 = reinterpret_cast<const float4*>(x);
#pragma unroll
        for (int i = t; i < 1024; i += NT) {
            float4 v = x4[i];
            lsum += v.x + v.y + v.z + v.w;
            lsq += v.x * v.x + v.y * v.y + v.z * v.z + v.w * v.w;
        }
        sm[t] = lsum; sm[512 + t] = lsq;
        __syncthreads();
        for (int s = 256; s > 0; s >>= 1) {
            if (t < s) { sm[t] += sm[t + s]; sm[512 + t] += sm[512 + t + s]; }
            __syncthreads();
        }
        float mean = sm[0] * (1.0f / H);
        float var = sm[512] * (1.0f / H) - mean * mean;
        float rs = rsqrtf(var + 1e-5f);
        __syncthreads();

        int c = b;                       // 128 chunks of 32 rows
        if (c < 128) {
            if (t < 32) {
                int i = c * 32 + t;
                float xn = (x[i] - mean) * rs * ln1_w[i] + ln1_b[i];
                float sx = s1[i] - xn;
                g_xn[i] = xn;
                g_sx[i] = sx;
                d_out[H + i] = xn;       // state1_out
                sm[1024 + t] = xn + sx * tmx[i];
            }
            __syncthreads();
            if (t < 320) {
                float acc = 0.f;
#pragma unroll 8
                for (int i = 0; i < 32; i++)
                    acc += sm[1024 + i] * Wmaa1[(size_t)(c * 32 + i) * 320 + t];
                g_maa_part[c][t] = acc;
            }
        } else {
            // idle blocks: prefetch front of Wr/Wk/Wv/Wg into L2 (~16 MB total)
            int bb = c - 128;                      // 0..315
            const size_t PF = (size_t)4 << 20;     // 4 MB per matrix
            size_t share = PF / 316;
            size_t start = (size_t)bb * share;
            const float* Ws0 = Wr; const float* Ws1 = Wk;
            const float* Ws2 = Wv; const float* Ws3 = Wg;
            for (size_t off = (size_t)t * 128; off < share; off += (size_t)NT * 128) {
                asm volatile("prefetch.global.L2 [%0];" :: "l"((const char*)Ws0 + start + off));
                asm volatile("prefetch.global.L2 [%0];" :: "l"((const char*)Ws1 + start + off));
                asm volatile("prefetch.global.L2 [%0];" :: "l"((const char*)Ws2 + start + off));
                asm volatile("prefetch.global.L2 [%0];" :: "l"((const char*)Ws3 + start + off));
            }
        }
    }
    grid_barrier();

    // ================= Phase B: mix = tanh(reduce), m = xn + sx*(mix@Wmaa2 + maa) =====
    {
        int u = b;                       // 80 units
        if (u < 80) {
            int s5 = u >> 4, chunk = u & 15;
            int tt = t & 63, seg = t >> 6;
            float a = 0.f;
#pragma unroll
            for (int cc = seg * 16; cc < seg * 16 + 16; cc++)
                a += g_maa_part[cc][s5 * 64 + tt];
            sm[t] = a;
            __syncthreads();
            if (t < 64) {
                float m = sm[t];
#pragma unroll
                for (int g2 = 1; g2 < 8; g2++) m += sm[g2 * 64 + t];
                sm[512 + t] = tanhf(m);
            }
            __syncthreads();
            if (t < 256) {
                int hh = chunk * 256 + t;
                float acc = 0.f;
#pragma unroll 8
                for (int e = 0; e < 64; e++)
                    acc += sm[512 + e] * Wmaa2[(size_t)(s5 * 64 + e) * H + hh];
                const float* maa = (s5 == 0) ? tmw : (s5 == 1) ? tmk : (s5 == 2) ? tmv
                                  : (s5 == 3) ? tmr : tmg;
                g_m[s5][hh] = g_xn[hh] + g_sx[hh] * (acc + maa[hh]);
            }
        }
    }
    grid_barrier();

    // ================= Phase C: r/k/v/g full-K GEMV, 1024 fine units + 64 Wd1 =========
    // u < 1024: mat = u>>8, stripe = u&255 (4 f4 cols). Cached per-mat vector in smem.
    {
        int last_mat = -1;
        for (;;) {
            __syncthreads();
            if (t == 0) s_u = atomicAdd(&g_tickC, 1u);
            __syncthreads();
            unsigned u = s_u;
            if (u >= 1088u) break;
            if (u < 1024u) {
                int mat = (int)(u >> 8);
                int stripe = (int)(u & 255);
                if (mat != last_mat) {
                    const float* vec = (mat == 0) ? g_m[3] : (mat == 1) ? g_m[1]
                                      : (mat == 2) ? g_m[2] : g_m[4];
                    float4* sv4 = reinterpret_cast<float4*>(sm);
                    const float4* v4 = reinterpret_cast<const float4*>(vec);
#pragma unroll
                    for (int i = t; i < 1024; i += NT) sv4[i] = v4[i];
                    last_mat = mat;
                    __syncthreads();
                }
                const float* W = (mat == 0) ? Wr : (mat == 1) ? Wk : (mat == 2) ? Wv : Wg;
                const float4* W4 = reinterpret_cast<const float4*>(W);
                int cg = t & 3, rg = t >> 2;           // 4 f4-cols x 128 row-groups
                int colbase = stripe * 4 + cg;
                float4 acc = make_float4(0.f, 0.f, 0.f, 0.f);
#pragma unroll 8
                for (int i = 0; i < 32; i++) {
                    int row = rg + i * 128;
                    f4_fma(acc, sm[row], W4[(size_t)row * 1024 + colbase]);
                }
                // warp reduce over rg low bits (lane bits 2..4)
                acc.x += __shfl_xor_sync(0xffffffffu, acc.x, 4);
                acc.y += __shfl_xor_sync(0xffffffffu, acc.y, 4);
                acc.z += __shfl_xor_sync(0xffffffffu, acc.z, 4);
                acc.w += __shfl_xor_sync(0xffffffffu, acc.w, 4);
                acc.x += __shfl_xor_sync(0xffffffffu, acc.x, 8);
                acc.y += __shfl_xor_sync(0xffffffffu, acc.y, 8);
                acc.z += __shfl_xor_sync(0xffffffffu, acc.z, 8);
                acc.w += __shfl_xor_sync(0xffffffffu, acc.w, 8);
                acc.x += __shfl_xor_sync(0xffffffffu, acc.x, 16);
                acc.y += __shfl_xor_sync(0xffffffffu, acc.y, 16);
                acc.z += __shfl_xor_sync(0xffffffffu, acc.z, 16);
                acc.w += __shfl_xor_sync(0xffffffffu, acc.w, 16);
                float4* sred = reinterpret_cast<float4*>(sm + 4096);
                int lane = t & 31, w = t >> 5;
                if (lane < 4) sred[w * 4 + cg] = acc;
                __syncthreads();
                if (t < 4) {
                    float4 a = sred[t];
#pragma unroll
                    for (int w2 = 1; w2 < 16; w2++) f4_add(a, sred[w2 * 4 + t]);
                    if (mat == 3) {
                        a.x = a.x / (1.0f + expf(-a.x));
                        a.y = a.y / (1.0f + expf(-a.y));
                        a.z = a.z / (1.0f + expf(-a.z));
                        a.w = a.w / (1.0f + expf(-a.w));
                    }
                    reinterpret_cast<float4*>(g_rkvg[mat])[stripe * 4 + t] = a;
                }
            } else {
                int split = (int)u - 1024;   // 64 rows
                if (t < 64) sm[4352 + t] = g_m[0][split * 64 + t];
                __syncthreads();
                int col = t & 127, seg = t >> 7;   // 4 segs x 16 rows
                float acc = 0.f;
#pragma unroll
                for (int i = 0; i < 16; i++)
                    acc += sm[4352 + seg * 16 + i]
                         * Wd1[(size_t)(split * 64 + seg * 16 + i) * TD + col];
                sm[4416 + t] = acc;
                __syncthreads();
                if (t < TD)
                    g_wd1_part[split][t] = sm[4416 + t] + sm[4416 + t + 128]
                                         + sm[4416 + t + 256] + sm[4416 + t + 384];
            }
        }
    }
    grid_barrier();

    // ================= Phase D: heads (blocks 0..63); others prefetch Wo ==============
    {
        int h = b;
        if (h < 64) {
            int base = h * HS;
            float* r_s = sm + 1152;
            float* k_s = sm + 1216;
            float* v_s = sm + 1280;
            float* td_s = sm + 1344;
            float* prod = sm + 1408;
            float* part = sm + 1472;   // 512
            float* red = sm + 1984;
            float* red2 = sm + 2048;

            // wd1 reduce -> tanh
            {
                int col = t & 127, sg = t >> 7;    // 4 segs x 16 splits
                float a = 0.f;
#pragma unroll
                for (int s = sg * 16; s < sg * 16 + 16; s++)
                    a += g_wd1_part[s][col];
                sm[t] = a;
            }
            __syncthreads();
            if (t < TD)
                sm[512 + t] = tanhf(sm[t] + sm[t + 128] + sm[t + 256] + sm[t + 384]);
            __syncthreads();
            // Wd2 stripe for this head's 64 cols
            {
                int d = t & 63, sg = t >> 6;       // 8 segs x 16 e
                float a = 0.f;
#pragma unroll
                for (int e = sg * 16; e < sg * 16 + 16; e++)
                    a += sm[512 + e] * Wd2[(size_t)e * H + base + d];
                sm[640 + t] = a;
            }
            __syncthreads();
            if (t < 64) {
                float s = sm[640 + t] + sm[640 + 64 + t] + sm[640 + 128 + t] + sm[640 + 192 + t]
                        + sm[640 + 256 + t] + sm[640 + 320 + t] + sm[640 + 384 + t] + sm[640 + 448 + t];
                td_s[t] = expf(-expf(tdec[base + t] + s));
                float rv = g_rkvg[0][base + t];
                float kv = g_rkvg[1][base + t];
                r_s[t] = rv;
                k_s[t] = kv;
                v_s[t] = g_rkvg[2][base + t];
                prod[t] = rv * kv * faaaa[base + t];
            }
            __syncthreads();
            if (t < 32) prod[t] += prod[t + 32];
            __syncthreads();
            if (t < 16) prod[t] += prod[t + 16];
            __syncthreads();
            if (t < 8) prod[t] += prod[t + 8];
            __syncthreads();
            if (t < 4) prod[t] += prod[t + 4];
            __syncthreads();
            if (t < 2) prod[t] += prod[t + 2];
            __syncthreads();
            if (t == 0) prod[0] += prod[1];
            __syncthreads();
            float dot1 = prod[0];

            int d = t & 63, q = t >> 6;            // 8 groups x 8 kk
            const float* s2 = state2 + (size_t)h * HS * HS;
            float* s2o = d_out + 2 * H + (size_t)h * HS * HS;
            float vv = v_s[d];
            float acc = 0.f;
#pragma unroll
            for (int kk = q * 8; kk < q * 8 + 8; kk++) {
                float s2v = s2[kk * HS + d];
                acc += r_s[kk] * s2v;
                s2o[kk * HS + d] = k_s[kk] * vv + s2v * td_s[kk];
            }
            part[q * 64 + d] = acc;
            __syncthreads();

            if (t < 64) {
                float out_d = v_s[t] * dot1;
#pragma unroll
                for (int q2 = 0; q2 < 8; q2++) out_d += part[q2 * 64 + t];
                red[t] = out_d;
                red2[t] = out_d * out_d;
                part[t] = out_d;   // stash
            }
            __syncthreads();
            if (t < 32) { red[t] += red[t + 32]; red2[t] += red2[t + 32]; }
            __syncthreads();
            if (t < 16) { red[t] += red[t + 16]; red2[t] += red2[t + 16]; }
            __syncthreads();
            if (t < 8) { red[t] += red[t + 8]; red2[t] += red2[t + 8]; }
            __syncthreads();
            if (t < 4) { red[t] += red[t + 4]; red2[t] += red2[t + 4]; }
            __syncthreads();
            if (t < 2) { red[t] += red[t + 2]; red2[t] += red2[t + 2]; }
            __syncthreads();
            if (t == 0) { red[0] += red[1]; red2[0] += red2[1]; }
            __syncthreads();
            if (t < 64) {
                float mean = red[0] * (1.0f / HS);
                float var = red2[0] * (1.0f / HS) - mean * mean;
                float o = (part[t] - mean) * rsqrtf(var + 1e-5f) * lnxw[base + t] + lnxb[base + t];
                g_gx[base + t] = o * g_rkvg[3][base + t];
            }
        } else {
            // idle blocks: prefetch front ~32 MB of Wo into L2
            int bb = b - 64;                        // 0..379
            const size_t PF = (size_t)32 << 20;
            size_t chunk = PF / 380;
            const char* p = (const char*)Wo + (size_t)bb * chunk;
            for (size_t off = (size_t)t * 128; off < chunk; off += (size_t)NT * 128)
                asm volatile("prefetch.global.L2 [%0];" :: "l"(p + off));
        }
    }
    grid_barrier();

    // ================= Phase E: Wo full-K GEMV + residual (512 units, vec cached) =====
    {
        float4* sv4 = reinterpret_cast<float4*>(sm);
        const float4* gx4 = reinterpret_cast<const float4*>(g_gx);
#pragma unroll
        for (int i = t; i < 1024; i += NT) sv4[i] = gx4[i];
        __syncthreads();
        const float4* W4 = reinterpret_cast<const float4*>(Wo);
        for (;;) {
            __syncthreads();
            if (t == 0) s_u = atomicAdd(&g_tickE, 1u);
            __syncthreads();
            unsigned u = s_u;
            if (u >= 512u) break;
            int cg = t & 1, rg = t >> 1;            // 2 f4-cols x 256 row-groups
            int colbase = (int)u * 2 + cg;
            float4 acc = make_float4(0.f, 0.f, 0.f, 0.f);
#pragma unroll 8
            for (int i = 0; i < 16; i++) {
                int row = rg + i * 256;
                f4_fma(acc, sm[row], W4[(size_t)row * 1024 + colbase]);
            }
            // warp reduce over rg low bits (lane bits 1..4)
            acc.x += __shfl_xor_sync(0xffffffffu, acc.x, 2);
            acc.y += __shfl_xor_sync(0xffffffffu, acc.y, 2);
            acc.z += __shfl_xor_sync(0xffffffffu, acc.z, 2);
            acc.w += __shfl_xor_sync(0xffffffffu, acc.w, 2);
            acc.x += __shfl_xor_sync(0xffffffffu, acc.x, 4);
            acc.y += __shfl_xor_sync(0xffffffffu, acc.y, 4);
            acc.z += __shfl_xor_sync(0xffffffffu, acc.z, 4);
            acc.w += __shfl_xor_sync(0xffffffffu, acc.w, 4);
            acc.x += __shfl_xor_sync(0xffffffffu, acc.x, 8);
            acc.y += __shfl_xor_sync(0xffffffffu, acc.y, 8);
            acc.z += __shfl_xor_sync(0xffffffffu, acc.z, 8);
            acc.w += __shfl_xor_sync(0xffffffffu, acc.w, 8);
            acc.x += __shfl_xor_sync(0xffffffffu, acc.x, 16);
            acc.y += __shfl_xor_sync(0xffffffffu, acc.y, 16);
            acc.z += __shfl_xor_sync(0xffffffffu, acc.z, 16);
            acc.w += __shfl_xor_sync(0xffffffffu, acc.w, 16);
            float4* sred = reinterpret_cast<float4*>(sm + 4096);
            int lane = t & 31, w = t >> 5;
            if (lane < 2) sred[w * 2 + cg] = acc;
            __syncthreads();
            if (t < 2) {
                float4 a = sred[t];
#pragma unroll
                for (int w2 = 1; w2 < 16; w2++) f4_add(a, sred[w2 * 2 + t]);
                float4 xr = reinterpret_cast<const float4*>(x)[(int)u * 2 + t];
                a.x += xr.x; a.y += xr.y; a.z += xr.z; a.w += xr.w;
                reinterpret_cast<float4*>(d_out)[(int)u * 2 + t] = a;
            }
        }
    }
}

extern "C" void kernel_launch(void* const* d_in, const int* in_sizes, int n_in,
                              void* d_out, int out_size) {
    const float* x      = (const float*)d_in[0];
    const float* state1 = (const float*)d_in[1];
    const float* state2 = (const float*)d_in[2];
    const float* ln1_w  = (const float*)d_in[3];
    const float* ln1_b  = (const float*)d_in[4];
    const float* tmx    = (const float*)d_in[5];
    const float* tmw    = (const float*)d_in[6];
    const float* tmk    = (const float*)d_in[7];
    const float* tmv    = (const float*)d_in[8];
    const float* tmr    = (const float*)d_in[9];
    const float* tmg    = (const float*)d_in[10];
    const float* Wmaa1  = (const float*)d_in[11];
    const float* Wmaa2  = (const float*)d_in[12];
    const float* tdec   = (const float*)d_in[13];
    const float* Wd1    = (const float*)d_in[14];
    const float* Wd2    = (const float*)d_in[15];
    const float* faaaa  = (const float*)d_in[16];
    const float* Wr     = (const float*)d_in[17];
    const float* Wk     = (const float*)d_in[18];
    const float* Wv     = (const float*)d_in[19];
    const float* Wg     = (const float*)d_in[20];
    const float* Wo     = (const float*)d_in[21];
    const float* lnxw   = (const float*)d_in[22];
    const float* lnxb   = (const float*)d_in[23];
    float* out = (float*)d_out;

    k_reset<<<1, 32>>>();
    k_mega<<<GRID, NT>>>(x, state1, state2, ln1_w, ln1_b, tmx, tmw, tmk, tmv, tmr, tmg,
                         Wmaa1, Wmaa2, tdec, Wd1, Wd2, faaaa, Wr, Wk, Wv, Wg, Wo,
                         lnxw, lnxb, out);
}

// round 11
// speedup vs baseline: 1.2101x; 1.2101x over previous
#include <cuda_runtime.h>
#include <math.h>

#define H 4096
#define HS 64
#define NH 64
#define TM 64
#define TD 128
#define GRID 296
#define NT 512

// ---------------- scratch (device globals) ----------------
__device__ float g_xn[H];
__device__ float g_sx[H];
__device__ float g_maa_part[128][5 * TM];
__device__ float g_m[5][H];
__device__ float g_wd1_part[64][TD];
__device__ float g_rkvg[4][H];
__device__ float g_td[H];
__device__ float g_gx[H];

__device__ unsigned long long g_bar = 0ULL;   // monotone across launches
__device__ unsigned int g_tickC;
__device__ unsigned int g_tickE;
__device__ unsigned int g_wd1done;

__device__ __forceinline__ void grid_barrier() {
    __syncthreads();
    if (threadIdx.x == 0) {
        __threadfence();
        unsigned long long ticket = atomicAdd(&g_bar, 1ULL);
        unsigned long long goal = (ticket / GRID + 1ULL) * GRID;
        while (*((volatile unsigned long long*)&g_bar) < goal) { }
        __threadfence();
    }
    __syncthreads();
}

__device__ __forceinline__ void f4_fma(float4& a, float m, const float4& w) {
    a.x += m * w.x; a.y += m * w.y; a.z += m * w.z; a.w += m * w.w;
}
__device__ __forceinline__ void f4_add(float4& a, const float4& b) {
    a.x += b.x; a.y += b.y; a.z += b.z; a.w += b.w;
}

__global__ __launch_bounds__(NT, 2)
void k_mega(const float* __restrict__ x,
            const float* __restrict__ s1,
            const float* __restrict__ state2,
            const float* __restrict__ ln1_w,
            const float* __restrict__ ln1_b,
            const float* __restrict__ tmx,
            const float* __restrict__ tmw,
            const float* __restrict__ tmk,
            const float* __restrict__ tmv,
            const float* __restrict__ tmr,
            const float* __restrict__ tmg,
            const float* __restrict__ Wmaa1,
            const float* __restrict__ Wmaa2,
            const float* __restrict__ tdec,
            const float* __restrict__ Wd1,
            const float* __restrict__ Wd2,
            const float* __restrict__ faaaa,
            const float* __restrict__ Wr,
            const float* __restrict__ Wk,
            const float* __restrict__ Wv,
            const float* __restrict__ Wg,
            const float* __restrict__ Wo,
            const float* __restrict__ lnxw,
            const float* __restrict__ lnxb,
            float* __restrict__ d_out) {
    __shared__ __align__(16) float sm[5120];   // 20 KB
    __shared__ unsigned s_u;
    int t = threadIdx.x;
    int b = blockIdx.x;

    // reset per-launch counters (previous launch fully drained them; A->B barrier publishes)
    if (b == 0 && t == 0) {
        g_tickC = 0u;
        g_tickE = 0u;
        g_wd1done = 0u;
    }

    // ================= Phase A: LN stats (redundant) + token shift + maa1 partials ====
    {
        float lsum = 0.f, lsq = 0.f;
        const float4* x4 = reinterpret_cast<const float4*>(x);
#pragma unroll
        for (int i = t; i < 1024; i += NT) {
            float4 v = x4[i];
            lsum += v.x + v.y + v.z + v.w;
            lsq += v.x * v.x + v.y * v.y + v.z * v.z + v.w * v.w;
        }
        sm[t] = lsum; sm[512 + t] = lsq;
        __syncthreads();
        for (int s = 256; s > 0; s >>= 1) {
            if (t < s) { sm[t] += sm[t + s]; sm[512 + t] += sm[512 + t + s]; }
            __syncthreads();
        }
        float mean = sm[0] * (1.0f / H);
        float var = sm[512] * (1.0f / H) - mean * mean;
        float rs = rsqrtf(var + 1e-5f);
        __syncthreads();

        int c = b;                       // 128 chunks of 32 rows
        if (c < 128) {
            if (t < 32) {
                int i = c * 32 + t;
                float xn = (x[i] - mean) * rs * ln1_w[i] + ln1_b[i];
                float sx = s1[i] - xn;
                g_xn[i] = xn;
                g_sx[i] = sx;
                d_out[H + i] = xn;       // state1_out
                sm[1024 + t] = xn + sx * tmx[i];
            }
            __syncthreads();
            if (t < 320) {
                float acc = 0.f;
#pragma unroll 8
                for (int i = 0; i < 32; i++)
                    acc += sm[1024 + i] * Wmaa1[(size_t)(c * 32 + i) * 320 + t];
                g_maa_part[c][t] = acc;
            }
        }
    }
    grid_barrier();

    // ================= Phase B: mix = tanh(reduce), m = xn + sx*(mix@Wmaa2 + maa) =====
    // 160 units: s5 = u>>5, chunk = u&31 (128 cols). 512 threads: 4 e-segs x 128 cols.
    {
        int u = b;
        if (u < 160) {
            int s5 = u >> 5, chunk = u & 31;
            // mix for this s5: reduce 128 partial chunks (8 segs of 16) then tanh
            {
                int tt = t & 63, seg = t >> 6;
                float a = 0.f;
#pragma unroll
                for (int cc = seg * 16; cc < seg * 16 + 16; cc++)
                    a += g_maa_part[cc][s5 * 64 + tt];
                sm[t] = a;
            }
            __syncthreads();
            if (t < 64) {
                float m = sm[t];
#pragma unroll
                for (int g2 = 1; g2 < 8; g2++) m += sm[g2 * 64 + t];
                sm[512 + t] = tanhf(m);
            }
            __syncthreads();
            // Wmaa2 stripe: 128 cols, 4 e-segs of 16
            {
                int col = t & 127, seg = t >> 7;
                int hh = chunk * 128 + col;
                float a = 0.f;
#pragma unroll
                for (int e = seg * 16; e < seg * 16 + 16; e++)
                    a += sm[512 + e] * Wmaa2[(size_t)(s5 * 64 + e) * H + hh];
                sm[640 + t] = a;
            }
            __syncthreads();
            if (t < 128) {
                int hh = chunk * 128 + t;
                float acc = sm[640 + t] + sm[640 + t + 128] + sm[640 + t + 256] + sm[640 + t + 384];
                const float* maa = (s5 == 0) ? tmw : (s5 == 1) ? tmk : (s5 == 2) ? tmv
                                  : (s5 == 3) ? tmr : tmg;
                g_m[s5][hh] = g_xn[hh] + g_sx[hh] * (acc + maa[hh]);
            }
        }
    }
    grid_barrier();

    // ================= Phase C (ticket): Wd1 -> big mats -> gated decay ===============
    // u < 64: Wd1 split u. 64 <= u < 576: big mats. 576 <= u < 608: decay (gated).
    for (;;) {
        __syncthreads();
        if (t == 0) s_u = atomicAdd(&g_tickC, 1u);
        __syncthreads();
        unsigned u = s_u;
        if (u >= 608u) break;
        if (u < 64u) {
            int split = (int)u;                    // 64 rows
            if (t < 64) sm[4352 + t] = g_m[0][split * 64 + t];
            __syncthreads();
            int col = t & 127, seg = t >> 7;       // 4 segs x 16 rows
            float acc = 0.f;
#pragma unroll
            for (int i = 0; i < 16; i++)
                acc += sm[4352 + seg * 16 + i]
                     * Wd1[(size_t)(split * 64 + seg * 16 + i) * TD + col];
            sm[4416 + t] = acc;
            __syncthreads();
            if (t < TD)
                g_wd1_part[split][t] = sm[4416 + t] + sm[4416 + t + 128]
                                     + sm[4416 + t + 256] + sm[4416 + t + 384];
            __threadfence();
            __syncthreads();
            if (t == 0) atomicAdd(&g_wd1done, 1u);
        } else if (u < 576u) {
            int mat = (int)((u - 64) & 3);
            int stripe = (int)((u - 64) >> 2);     // 0..127, 8 f4 cols each
            const float* vec = (mat == 0) ? g_m[3] : (mat == 1) ? g_m[1]
                              : (mat == 2) ? g_m[2] : g_m[4];
            const float* W = (mat == 0) ? Wr : (mat == 1) ? Wk : (mat == 2) ? Wv : Wg;
            float4* sv4 = reinterpret_cast<float4*>(sm);
            const float4* v4 = reinterpret_cast<const float4*>(vec);
#pragma unroll
            for (int i = t; i < 1024; i += NT) sv4[i] = v4[i];
            __syncthreads();
            const float4* W4 = reinterpret_cast<const float4*>(W);
            int cg = t & 7, rg = t >> 3;           // 8 f4-cols x 64 row-groups
            int colbase = stripe * 8 + cg;
            float4 acc0 = make_float4(0.f, 0.f, 0.f, 0.f);
            float4 acc1 = make_float4(0.f, 0.f, 0.f, 0.f);
#pragma unroll 4
            for (int i = 0; i < 32; i++) {
                int r0 = i * 64 + rg;
                int r1 = (i + 32) * 64 + rg;
                f4_fma(acc0, sm[r0], W4[(size_t)r0 * 1024 + colbase]);
                f4_fma(acc1, sm[r1], W4[(size_t)r1 * 1024 + colbase]);
            }
            f4_add(acc0, acc1);
            acc0.x += __shfl_xor_sync(0xffffffffu, acc0.x, 8);
            acc0.y += __shfl_xor_sync(0xffffffffu, acc0.y, 8);
            acc0.z += __shfl_xor_sync(0xffffffffu, acc0.z, 8);
            acc0.w += __shfl_xor_sync(0xffffffffu, acc0.w, 8);
            acc0.x += __shfl_xor_sync(0xffffffffu, acc0.x, 16);
            acc0.y += __shfl_xor_sync(0xffffffffu, acc0.y, 16);
            acc0.z += __shfl_xor_sync(0xffffffffu, acc0.z, 16);
            acc0.w += __shfl_xor_sync(0xffffffffu, acc0.w, 16);
            float4* sred = reinterpret_cast<float4*>(sm + 4096);
            int w = t >> 5;
            if ((t & 31) < 8) sred[w * 8 + cg] = acc0;
            __syncthreads();
            if (t < 8) {
                float4 a = sred[t];
#pragma unroll
                for (int w2 = 1; w2 < 16; w2++) f4_add(a, sred[w2 * 8 + t]);
                if (mat == 3) {
                    a.x = a.x / (1.0f + expf(-a.x));
                    a.y = a.y / (1.0f + expf(-a.y));
                    a.z = a.z / (1.0f + expf(-a.z));
                    a.w = a.w / (1.0f + expf(-a.w));
                }
                reinterpret_cast<float4*>(g_rkvg[mat])[stripe * 8 + t] = a;
            }
        } else {
            // decay unit: 32 units x 128 cols
            int du = (int)u - 576;
            if (t == 0) {
                while (*((volatile unsigned*)&g_wd1done) < 64u) { }
            }
            __syncthreads();
            __threadfence();
            // sdd = tanh(reduce over 64 splits), computed redundantly per unit
            {
                int col = t & 127, sg = t >> 7;    // 4 segs x 16 splits
                float a = 0.f;
#pragma unroll
                for (int s = sg * 16; s < sg * 16 + 16; s++)
                    a += g_wd1_part[s][col];
                sm[4096 + t] = a;
            }
            __syncthreads();
            if (t < TD)
                sm[4608 + t] = tanhf(sm[4096 + t] + sm[4096 + t + 128]
                                   + sm[4096 + t + 256] + sm[4096 + t + 384]);
            __syncthreads();
            // Wd2 stripe: 128 cols, 4 e-segs of 32
            {
                int col = t & 127, sg = t >> 7;
                int j = du * 128 + col;
                float a = 0.f;
#pragma unroll 8
                for (int e = sg * 32; e < sg * 32 + 32; e++)
                    a += sm[4608 + e] * Wd2[(size_t)e * H + j];
                sm[4096 + t] = a;
            }
            __syncthreads();
            if (t < 128) {
                int j = du * 128 + t;
                float s = sm[4096 + t] + sm[4096 + t + 128] + sm[4096 + t + 256] + sm[4096 + t + 384];
                g_td[j] = expf(-expf(tdec[j] + s));
            }
        }
    }
    grid_barrier();

    // ================= Phase D: heads only (blocks 0..63) =============================
    {
        int h = b;
        if (h < 64) {
            int base = h * HS;
            float* r_s = sm + 1152;
            float* k_s = sm + 1216;
            float* v_s = sm + 1280;
            float* td_s = sm + 1344;
            float* prod = sm + 1408;
            float* part = sm + 1472;   // 512
            float* red = sm + 1984;
            float* red2 = sm + 2048;

            if (t < 64) {
                td_s[t] = g_td[base + t];
                float rv = g_rkvg[0][base + t];
                float kv = g_rkvg[1][base + t];
                r_s[t] = rv;
                k_s[t] = kv;
                v_s[t] = g_rkvg[2][base + t];
                prod[t] = rv * kv * faaaa[base + t];
            }
            __syncthreads();
            if (t < 32) prod[t] += prod[t + 32];
            __syncthreads();
            if (t < 16) prod[t] += prod[t + 16];
            __syncthreads();
            if (t < 8) prod[t] += prod[t + 8];
            __syncthreads();
            if (t < 4) prod[t] += prod[t + 4];
            __syncthreads();
            if (t < 2) prod[t] += prod[t + 2];
            __syncthreads();
            if (t == 0) prod[0] += prod[1];
            __syncthreads();
            float dot1 = prod[0];

            int d = t & 63, q = t >> 6;            // 8 groups x 8 kk
            const float* s2 = state2 + (size_t)h * HS * HS;
            float* s2o = d_out + 2 * H + (size_t)h * HS * HS;
            float vv = v_s[d];
            float acc = 0.f;
#pragma unroll
            for (int kk = q * 8; kk < q * 8 + 8; kk++) {
                float s2v = s2[kk * HS + d];
                acc += r_s[kk] * s2v;
                s2o[kk * HS + d] = k_s[kk] * vv + s2v * td_s[kk];
            }
            part[q * 64 + d] = acc;
            __syncthreads();

            if (t < 64) {
                float out_d = v_s[t] * dot1;
#pragma unroll
                for (int q2 = 0; q2 < 8; q2++) out_d += part[q2 * 64 + t];
                red[t] = out_d;
                red2[t] = out_d * out_d;
                part[t] = out_d;   // stash
            }
            __syncthreads();
            if (t < 32) { red[t] += red[t + 32]; red2[t] += red2[t + 32]; }
            __syncthreads();
            if (t < 16) { red[t] += red[t + 16]; red2[t] += red2[t + 16]; }
            __syncthreads();
            if (t < 8) { red[t] += red[t + 8]; red2[t] += red2[t + 8]; }
            __syncthreads();
            if (t < 4) { red[t] += red[t + 4]; red2[t] += red2[t + 4]; }
            __syncthreads();
            if (t < 2) { red[t] += red[t + 2]; red2[t] += red2[t + 2]; }
            __syncthreads();
            if (t == 0) { red[0] += red[1]; red2[0] += red2[1]; }
            __syncthreads();
            if (t < 64) {
                float mean = red[0] * (1.0f / HS);
                float var = red2[0] * (1.0f / HS) - mean * mean;
                float o = (part[t] - mean) * rsqrtf(var + 1e-5f) * lnxw[base + t] + lnxb[base + t];
                g_gx[base + t] = o * g_rkvg[3][base + t];
            }
        }
    }
    grid_barrier();

    // ================= Phase E: Wo full-K GEMV + residual (ticket, vec hoisted) =======
    {
        float4* sv4 = reinterpret_cast<float4*>(sm);
        const float4* gx4 = reinterpret_cast<const float4*>(g_gx);
#pragma unroll
        for (int i = t; i < 1024; i += NT) sv4[i] = gx4[i];
        __syncthreads();
        const float4* W4 = reinterpret_cast<const float4*>(Wo);
        for (;;) {
            __syncthreads();
            if (t == 0) s_u = atomicAdd(&g_tickE, 1u);
            __syncthreads();
            unsigned u = s_u;
            if (u >= 256u) break;
            int cg = t & 3, rg = t >> 2;           // 4 f4-cols x 128 row-groups
            int colbase = (int)u * 4 + cg;
            float4 acc0 = make_float4(0.f, 0.f, 0.f, 0.f);
            float4 acc1 = make_float4(0.f, 0.f, 0.f, 0.f);
#pragma unroll 4
            for (int i = 0; i < 16; i++) {
                int r0 = i * 128 + rg;
                int r1 = (i + 16) * 128 + rg;
                f4_fma(acc0, sm[r0], W4[(size_t)r0 * 1024 + colbase]);
                f4_fma(acc1, sm[r1], W4[(size_t)r1 * 1024 + colbase]);
            }
            f4_add(acc0, acc1);
            acc0.x += __shfl_xor_sync(0xffffffffu, acc0.x, 4);
            acc0.y += __shfl_xor_sync(0xffffffffu, acc0.y, 4);
            acc0.z += __shfl_xor_sync(0xffffffffu, acc0.z, 4);
            acc0.w += __shfl_xor_sync(0xffffffffu, acc0.w, 4);
            acc0.x += __shfl_xor_sync(0xffffffffu, acc0.x, 8);
            acc0.y += __shfl_xor_sync(0xffffffffu, acc0.y, 8);
            acc0.z += __shfl_xor_sync(0xffffffffu, acc0.z, 8);
            acc0.w += __shfl_xor_sync(0xffffffffu, acc0.w, 8);
            acc0.x += __shfl_xor_sync(0xffffffffu, acc0.x, 16);
            acc0.y += __shfl_xor_sync(0xffffffffu, acc0.y, 16);
            acc0.z += __shfl_xor_sync(0xffffffffu, acc0.z, 16);
            acc0.w += __shfl_xor_sync(0xffffffffu, acc0.w, 16);
            float4* sred = reinterpret_cast<float4*>(sm + 4096);
            int w = t >> 5;
            if ((t & 31) < 4) sred[w * 4 + cg] = acc0;
            __syncthreads();
            if (t < 4) {
                float4 a = sred[t];
#pragma unroll
                for (int w2 = 1; w2 < 16; w2++) f4_add(a, sred[w2 * 4 + t]);
                float4 xr = reinterpret_cast<const float4*>(x)[(int)u * 4 + t];
                a.x += xr.x; a.y += xr.y; a.z += xr.z; a.w += xr.w;
                reinterpret_cast<float4*>(d_out)[(int)u * 4 + t] = a;
            }
        }
    }
}

extern "C" void kernel_launch(void* const* d_in, const int* in_sizes, int n_in,
                              void* d_out, int out_size) {
    const float* x      = (const float*)d_in[0];
    const float* state1 = (const float*)d_in[1];
    const float* state2 = (const float*)d_in[2];
    const float* ln1_w  = (const float*)d_in[3];
    const float* ln1_b  = (const float*)d_in[4];
    const float* tmx    = (const float*)d_in[5];
    const float* tmw    = (const float*)d_in[6];
    const float* tmk    = (const float*)d_in[7];
    const float* tmv    = (const float*)d_in[8];
    const float* tmr    = (const float*)d_in[9];
    const float* tmg    = (const float*)d_in[10];
    const float* Wmaa1  = (const float*)d_in[11];
    const float* Wmaa2  = (const float*)d_in[12];
    const float* tdec   = (const float*)d_in[13];
    const float* Wd1    = (const float*)d_in[14];
    const float* Wd2    = (const float*)d_in[15];
    const float* faaaa  = (const float*)d_in[16];
    const float* Wr     = (const float*)d_in[17];
    const float* Wk     = (const float*)d_in[18];
    const float* Wv     = (const float*)d_in[19];
    const float* Wg     = (const float*)d_in[20];
    const float* Wo     = (const float*)d_in[21];
    const float* lnxw   = (const float*)d_in[22];
    const float* lnxb   = (const float*)d_in[23];
    float* out = (float*)d_out;

    k_mega<<<GRID, NT>>>(x, state1, state2, ln1_w, ln1_b, tmx, tmw, tmk, tmv, tmr, tmg,
                         Wmaa1, Wmaa2, tdec, Wd1, Wd2, faaaa, Wr, Wk, Wv, Wg, Wo,
                         lnxw, lnxb, out);
}

// round 12
// speedup vs baseline: 1.2362x; 1.0216x over previous
#include <cuda_runtime.h>
#include <math.h>

#define H 4096
#define HS 64
#define NH 64
#define TM 64
#define TD 128
#define GRID 296
#define NT 512

// smem: 4 cached vecs (16384 floats) + work area (2176 floats)
#define VECF 16384
#define WORKF 2176
#define SMEM_BYTES ((VECF + WORKF) * 4)

// ---------------- scratch (device globals) ----------------
__device__ float g_xn[H];
__device__ float g_sx[H];
__device__ float g_maa_part[128][5 * TM];
__device__ float g_m[5][H];
__device__ float g_wd1_part[64][TD];
__device__ float g_rkvg[4][H];
__device__ float g_td[H];
__device__ float g_gx[H];
__device__ float g_wo_part[NH * H];          // 1 MB partials

__device__ unsigned long long g_bar = 0ULL;  // monotone across launches
__device__ unsigned int g_tick;
__device__ unsigned int g_wd1done;
__device__ unsigned int g_wodone;
__device__ unsigned int g_headready[NH];

__device__ __forceinline__ void grid_barrier() {
    __syncthreads();
    if (threadIdx.x == 0) {
        __threadfence();
        unsigned long long ticket = atomicAdd(&g_bar, 1ULL);
        unsigned long long goal = (ticket / GRID + 1ULL) * GRID;
        while (*((volatile unsigned long long*)&g_bar) < goal) { }
        __threadfence();
    }
    __syncthreads();
}

__device__ __forceinline__ void f4_fma(float4& a, float m, const float4& w) {
    a.x += m * w.x; a.y += m * w.y; a.z += m * w.z; a.w += m * w.w;
}
__device__ __forceinline__ void f4_add(float4& a, const float4& b) {
    a.x += b.x; a.y += b.y; a.z += b.z; a.w += b.w;
}

// unit ranges
#define U_WD1_END 64u
#define U_DEC_END 96u
#define U_C_END   1120u
#define U_D_END   1184u
#define U_E_END   1696u
#define U_F_END   1728u

__global__ __launch_bounds__(NT, 2)
void k_mega(const float* __restrict__ x,
            const float* __restrict__ s1,
            const float* __restrict__ state2,
            const float* __restrict__ ln1_w,
            const float* __restrict__ ln1_b,
            const float* __restrict__ tmx,
            const float* __restrict__ tmw,
            const float* __restrict__ tmk,
            const float* __restrict__ tmv,
            const float* __restrict__ tmr,
            const float* __restrict__ tmg,
            const float* __restrict__ Wmaa1,
            const float* __restrict__ Wmaa2,
            const float* __restrict__ tdec,
            const float* __restrict__ Wd1,
            const float* __restrict__ Wd2,
            const float* __restrict__ faaaa,
            const float* __restrict__ Wr,
            const float* __restrict__ Wk,
            const float* __restrict__ Wv,
            const float* __restrict__ Wg,
            const float* __restrict__ Wo,
            const float* __restrict__ lnxw,
            const float* __restrict__ lnxb,
            float* __restrict__ d_out) {
    extern __shared__ __align__(16) float sm[];
    __shared__ unsigned s_u;
    int t = threadIdx.x;
    int b = blockIdx.x;

    // reset per-launch counters (published by the A->B barrier; used only after B barrier)
    if (b == 0) {
        if (t == 0) { g_tick = 0u; g_wd1done = 0u; g_wodone = 0u; }
        if (t < NH) g_headready[t] = 0u;
    }

    // ================= Phase A: LN stats (redundant) + token shift + maa1 partials ====
    {
        float lsum = 0.f, lsq = 0.f;
        const float4* x4 = reinterpret_cast<const float4*>(x);
#pragma unroll
        for (int i = t; i < 1024; i += NT) {
            float4 v = x4[i];
            lsum += v.x + v.y + v.z + v.w;
            lsq += v.x * v.x + v.y * v.y + v.z * v.z + v.w * v.w;
        }
        sm[t] = lsum; sm[512 + t] = lsq;
        __syncthreads();
        for (int s = 256; s > 0; s >>= 1) {
            if (t < s) { sm[t] += sm[t + s]; sm[512 + t] += sm[512 + t + s]; }
            __syncthreads();
        }
        float mean = sm[0] * (1.0f / H);
        float var = sm[512] * (1.0f / H) - mean * mean;
        float rs = rsqrtf(var + 1e-5f);
        __syncthreads();

        int c = b;                       // 128 chunks of 32 rows
        if (c < 128) {
            if (t < 32) {
                int i = c * 32 + t;
                float xn = (x[i] - mean) * rs * ln1_w[i] + ln1_b[i];
                float sx = s1[i] - xn;
                g_xn[i] = xn;
                g_sx[i] = sx;
                d_out[H + i] = xn;       // state1_out
                sm[1024 + t] = xn + sx * tmx[i];
            }
            __syncthreads();
            if (t < 320) {
                float acc = 0.f;
#pragma unroll 8
                for (int i = 0; i < 32; i++)
                    acc += sm[1024 + i] * Wmaa1[(size_t)(c * 32 + i) * 320 + t];
                g_maa_part[c][t] = acc;
            }
        }
    }
    grid_barrier();

    // ================= Phase B: mix = tanh(reduce), m = xn + sx*(mix@Wmaa2 + maa) =====
    {
        int u = b;
        if (u < 160) {
            int s5 = u >> 5, chunk = u & 31;
            {
                int tt = t & 63, seg = t >> 6;
                float a = 0.f;
#pragma unroll
                for (int cc = seg * 16; cc < seg * 16 + 16; cc++)
                    a += g_maa_part[cc][s5 * 64 + tt];
                sm[t] = a;
            }
            __syncthreads();
            if (t < 64) {
                float m = sm[t];
#pragma unroll
                for (int g2 = 1; g2 < 8; g2++) m += sm[g2 * 64 + t];
                sm[512 + t] = tanhf(m);
            }
            __syncthreads();
            {
                int col = t & 127, seg = t >> 7;
                int hh = chunk * 128 + col;
                float a = 0.f;
#pragma unroll
                for (int e = seg * 16; e < seg * 16 + 16; e++)
                    a += sm[512 + e] * Wmaa2[(size_t)(s5 * 64 + e) * H + hh];
                sm[640 + t] = a;
            }
            __syncthreads();
            if (t < 128) {
                int hh = chunk * 128 + t;
                float acc = sm[640 + t] + sm[640 + t + 128] + sm[640 + t + 256] + sm[640 + t + 384];
                const float* maa = (s5 == 0) ? tmw : (s5 == 1) ? tmk : (s5 == 2) ? tmv
                                  : (s5 == 3) ? tmr : tmg;
                g_m[s5][hh] = g_xn[hh] + g_sx[hh] * (acc + maa[hh]);
            }
        }
    }
    grid_barrier();

    // ================= cache the 4 big-GEMV vectors in smem (mat order r,k,v,g) ========
    {
        const float* srcs[4] = { g_m[3], g_m[1], g_m[2], g_m[4] };
#pragma unroll
        for (int v = 0; v < 4; v++) {
            float4* dst = reinterpret_cast<float4*>(sm + v * 4096);
            const float4* s4 = reinterpret_cast<const float4*>(srcs[v]);
#pragma unroll
            for (int i = t; i < 1024; i += NT) dst[i] = s4[i];
        }
        __syncthreads();
    }
    float* W_ = sm + VECF;

    // ================= dependency-gated ticket pool ===================================
    for (;;) {
        __syncthreads();
        if (t == 0) s_u = atomicAdd(&g_tick, 1u);
        __syncthreads();
        unsigned u = s_u;
        if (u >= U_F_END) break;

        if (u < U_WD1_END) {
            // ---- Wd1 split unit ----
            int split = (int)u;
            if (t < 64) W_[t] = g_m[0][split * 64 + t];
            __syncthreads();
            int col = t & 127, seg = t >> 7;       // 4 segs x 16 rows
            float acc = 0.f;
#pragma unroll
            for (int i = 0; i < 16; i++)
                acc += W_[seg * 16 + i]
                     * Wd1[(size_t)(split * 64 + seg * 16 + i) * TD + col];
            W_[64 + t] = acc;
            __syncthreads();
            if (t < TD)
                g_wd1_part[split][t] = W_[64 + t] + W_[64 + t + 128]
                                     + W_[64 + t + 256] + W_[64 + t + 384];
            __threadfence();
            __syncthreads();
            if (t == 0) atomicAdd(&g_wd1done, 1u);
        } else if (u < U_DEC_END) {
            // ---- decay unit: 128 cols = 2 heads ----
            int du = (int)u - 64;
            if (t == 0) { while (*((volatile unsigned*)&g_wd1done) < 64u) { } }
            __syncthreads();
            __threadfence();
            {
                int col = t & 127, sg = t >> 7;    // 4 segs x 16 splits
                float a = 0.f;
#pragma unroll
                for (int s = sg * 16; s < sg * 16 + 16; s++)
                    a += g_wd1_part[s][col];
                W_[t] = a;
            }
            __syncthreads();
            if (t < TD)
                W_[512 + t] = tanhf(W_[t] + W_[t + 128] + W_[t + 256] + W_[t + 384]);
            __syncthreads();
            {
                int col = t & 127, sg = t >> 7;    // 4 segs x 32 e
                int j = du * 128 + col;
                float a = 0.f;
#pragma unroll 8
                for (int e = sg * 32; e < sg * 32 + 32; e++)
                    a += W_[512 + e] * Wd2[(size_t)e * H + j];
                W_[640 + t] = a;
            }
            __syncthreads();
            if (t < 128) {
                int j = du * 128 + t;
                float s = W_[640 + t] + W_[640 + t + 128] + W_[640 + t + 256] + W_[640 + t + 384];
                g_td[j] = expf(-expf(tdec[j] + s));
            }
            __threadfence();
            __syncthreads();
            if (t == 0) {
                atomicAdd(&g_headready[du * 2], 1u);
                atomicAdd(&g_headready[du * 2 + 1], 1u);
            }
        } else if (u < U_C_END) {
            // ---- big-mat unit: head x mat x col-quarter (4 f4-cols, all 4096 rows) ----
            int c = (int)u - 96;
            int head = c >> 4, inner = c & 15, mat = inner & 3, q = inner >> 2;
            const float* W = (mat == 0) ? Wr : (mat == 1) ? Wk : (mat == 2) ? Wv : Wg;
            const float* vec = sm + mat * 4096;
            const float4* W4 = reinterpret_cast<const float4*>(W);
            int cg = t & 3, rg = t >> 2;           // 4 f4-cols x 128 row-groups
            int colbase = head * 16 + q * 4 + cg;
            float4 acc = make_float4(0.f, 0.f, 0.f, 0.f);
#pragma unroll 8
            for (int i = 0; i < 32; i++) {
                int row = rg + i * 128;
                f4_fma(acc, vec[row], W4[(size_t)row * 1024 + colbase]);
            }
            acc.x += __shfl_xor_sync(0xffffffffu, acc.x, 4);
            acc.y += __shfl_xor_sync(0xffffffffu, acc.y, 4);
            acc.z += __shfl_xor_sync(0xffffffffu, acc.z, 4);
            acc.w += __shfl_xor_sync(0xffffffffu, acc.w, 4);
            acc.x += __shfl_xor_sync(0xffffffffu, acc.x, 8);
            acc.y += __shfl_xor_sync(0xffffffffu, acc.y, 8);
            acc.z += __shfl_xor_sync(0xffffffffu, acc.z, 8);
            acc.w += __shfl_xor_sync(0xffffffffu, acc.w, 8);
            acc.x += __shfl_xor_sync(0xffffffffu, acc.x, 16);
            acc.y += __shfl_xor_sync(0xffffffffu, acc.y, 16);
            acc.z += __shfl_xor_sync(0xffffffffu, acc.z, 16);
            acc.w += __shfl_xor_sync(0xffffffffu, acc.w, 16);
            float4* sred = reinterpret_cast<float4*>(W_);
            int w = t >> 5;
            if ((t & 31) < 4) sred[w * 4 + cg] = acc;
            __syncthreads();
            if (t < 4) {
                float4 a = sred[t];
#pragma unroll
                for (int w2 = 1; w2 < 16; w2++) f4_add(a, sred[w2 * 4 + t]);
                if (mat == 3) {
                    a.x = a.x / (1.0f + expf(-a.x));
                    a.y = a.y / (1.0f + expf(-a.y));
                    a.z = a.z / (1.0f + expf(-a.z));
                    a.w = a.w / (1.0f + expf(-a.w));
                }
                reinterpret_cast<float4*>(g_rkvg[mat])[head * 16 + q * 4 + t] = a;
            }
            __threadfence();
            __syncthreads();
            if (t == 0) atomicAdd(&g_headready[head], 1u);
        } else if (u < U_D_END) {
            // ---- head unit (gated on 16 C units + decay = 17) ----
            int h = (int)u - 1120;
            if (t == 0) { while (*((volatile unsigned*)&g_headready[h]) < 17u) { } }
            __syncthreads();
            __threadfence();
            int base = h * HS;
            float* r_s = W_;
            float* k_s = W_ + 64;
            float* v_s = W_ + 128;
            float* td_s = W_ + 192;
            float* prod = W_ + 256;
            float* part = W_ + 320;   // 512
            float* red = W_ + 832;
            float* red2 = W_ + 896;
            if (t < 64) {
                td_s[t] = g_td[base + t];
                float rv = g_rkvg[0][base + t];
                float kv = g_rkvg[1][base + t];
                r_s[t] = rv;
                k_s[t] = kv;
                v_s[t] = g_rkvg[2][base + t];
                prod[t] = rv * kv * faaaa[base + t];
            }
            __syncthreads();
            if (t < 32) prod[t] += prod[t + 32];
            __syncthreads();
            if (t < 16) prod[t] += prod[t + 16];
            __syncthreads();
            if (t < 8) prod[t] += prod[t + 8];
            __syncthreads();
            if (t < 4) prod[t] += prod[t + 4];
            __syncthreads();
            if (t < 2) prod[t] += prod[t + 2];
            __syncthreads();
            if (t == 0) prod[0] += prod[1];
            __syncthreads();
            float dot1 = prod[0];

            int d = t & 63, q = t >> 6;            // 8 groups x 8 kk
            const float* s2 = state2 + (size_t)h * HS * HS;
            float* s2o = d_out + 2 * H + (size_t)h * HS * HS;
            float vv = v_s[d];
            float acc = 0.f;
#pragma unroll
            for (int kk = q * 8; kk < q * 8 + 8; kk++) {
                float s2v = s2[kk * HS + d];
                acc += r_s[kk] * s2v;
                s2o[kk * HS + d] = k_s[kk] * vv + s2v * td_s[kk];
            }
            part[q * 64 + d] = acc;
            __syncthreads();

            if (t < 64) {
                float out_d = v_s[t] * dot1;
#pragma unroll
                for (int q2 = 0; q2 < 8; q2++) out_d += part[q2 * 64 + t];
                red[t] = out_d;
                red2[t] = out_d * out_d;
                part[t] = out_d;   // stash
            }
            __syncthreads();
            if (t < 32) { red[t] += red[t + 32]; red2[t] += red2[t + 32]; }
            __syncthreads();
            if (t < 16) { red[t] += red[t + 16]; red2[t] += red2[t + 16]; }
            __syncthreads();
            if (t < 8) { red[t] += red[t + 8]; red2[t] += red2[t + 8]; }
            __syncthreads();
            if (t < 4) { red[t] += red[t + 4]; red2[t] += red2[t + 4]; }
            __syncthreads();
            if (t < 2) { red[t] += red[t + 2]; red2[t] += red2[t + 2]; }
            __syncthreads();
            if (t == 0) { red[0] += red[1]; red2[0] += red2[1]; }
            __syncthreads();
            if (t < 64) {
                float mean = red[0] * (1.0f / HS);
                float var = red2[0] * (1.0f / HS) - mean * mean;
                float o = (part[t] - mean) * rsqrtf(var + 1e-5f) * lnxw[base + t] + lnxb[base + t];
                g_gx[base + t] = o * g_rkvg[3][base + t];
            }
            __threadfence();
            __syncthreads();
            if (t == 0) atomicAdd(&g_headready[h], 1u);    // -> 18
        } else if (u < U_E_END) {
            // ---- Wo split-K unit: head h rows, 128 f4-col chunk (gated on gx) ----
            int e = (int)u - 1184;
            int h = e >> 3, chunk = e & 7;
            if (t == 0) { while (*((volatile unsigned*)&g_headready[h]) < 18u) { } }
            __syncthreads();
            __threadfence();
            if (t < 64) W_[t] = g_gx[h * 64 + t];
            __syncthreads();
            int col = t & 127, rs = t >> 7;        // 4 row-segs x 16 rows
            const float4* W4 = reinterpret_cast<const float4*>(Wo);
            float4 acc = make_float4(0.f, 0.f, 0.f, 0.f);
#pragma unroll
            for (int i = 0; i < 16; i++) {
                int gxi = rs * 16 + i;
                f4_fma(acc, W_[gxi], W4[(size_t)(h * 64 + gxi) * 1024 + chunk * 128 + col]);
            }
            float4* sred = reinterpret_cast<float4*>(W_ + 64);
            sred[rs * 128 + col] = acc;
            __syncthreads();
            if (t < 128) {
                float4 a = sred[t];
                f4_add(a, sred[128 + t]);
                f4_add(a, sred[256 + t]);
                f4_add(a, sred[384 + t]);
                reinterpret_cast<float4*>(g_wo_part + (size_t)h * H)[chunk * 128 + t] = a;
            }
            __threadfence();
            __syncthreads();
            if (t == 0) atomicAdd(&g_wodone, 1u);
        } else {
            // ---- final reduce + residual: 128 float cols ----
            int f = (int)u - 1696;
            if (t == 0) { while (*((volatile unsigned*)&g_wodone) < 512u) { } }
            __syncthreads();
            __threadfence();
            int col = t & 127, hs = t >> 7;        // 4 segs x 16 heads
            int j = f * 128 + col;
            float a = 0.f;
#pragma unroll
            for (int hh = hs * 16; hh < hs * 16 + 16; hh++)
                a += g_wo_part[(size_t)hh * H + j];
            W_[t] = a;
            __syncthreads();
            if (t < 128) {
                int jj = f * 128 + t;
                d_out[jj] = x[jj] + W_[t] + W_[t + 128] + W_[t + 256] + W_[t + 384];
            }
        }
    }
}

extern "C" void kernel_launch(void* const* d_in, const int* in_sizes, int n_in,
                              void* d_out, int out_size) {
    const float* x      = (const float*)d_in[0];
    const float* state1 = (const float*)d_in[1];
    const float* state2 = (const float*)d_in[2];
    const float* ln1_w  = (const float*)d_in[3];
    const float* ln1_b  = (const float*)d_in[4];
    const float* tmx    = (const float*)d_in[5];
    const float* tmw    = (const float*)d_in[6];
    const float* tmk    = (const float*)d_in[7];
    const float* tmv    = (const float*)d_in[8];
    const float* tmr    = (const float*)d_in[9];
    const float* tmg    = (const float*)d_in[10];
    const float* Wmaa1  = (const float*)d_in[11];
    const float* Wmaa2  = (const float*)d_in[12];
    const float* tdec   = (const float*)d_in[13];
    const float* Wd1    = (const float*)d_in[14];
    const float* Wd2    = (const float*)d_in[15];
    const float* faaaa  = (const float*)d_in[16];
    const float* Wr     = (const float*)d_in[17];
    const float* Wk     = (const float*)d_in[18];
    const float* Wv     = (const float*)d_in[19];
    const float* Wg     = (const float*)d_in[20];
    const float* Wo     = (const float*)d_in[21];
    const float* lnxw   = (const float*)d_in[22];
    const float* lnxb   = (const float*)d_in[23];
    float* out = (float*)d_out;

    static int smem_set = 0;
    if (!smem_set) {
        cudaFuncSetAttribute(k_mega, cudaFuncAttributeMaxDynamicSharedMemorySize, SMEM_BYTES);
        smem_set = 1;
    }
    k_mega<<<GRID, NT, SMEM_BYTES>>>(x, state1, state2, ln1_w, ln1_b, tmx, tmw, tmk, tmv,
                                     tmr, tmg, Wmaa1, Wmaa2, tdec, Wd1, Wd2, faaaa,
                                     Wr, Wk, Wv, Wg, Wo, lnxw, lnxb, out);
}